// round 1
// baseline (speedup 1.0000x reference)
#include <cuda_runtime.h>

// Problem: z [N,256] fp32, p [N,256] fp32.
// res_i = sum_j softmax(z_i)_j * p_ij ; out = mean_i 2*(1 - sqrt(res_i))

#define D 256
#define WARPS_PER_BLOCK 8
#define THREADS (WARPS_PER_BLOCK * 32)
#define MAX_BLOCKS 32768   // 262144 / 8

__device__ float g_partials[MAX_BLOCKS];

__global__ __launch_bounds__(THREADS)
void row_loss_kernel(const float* __restrict__ z,
                     const float* __restrict__ p,
                     int nrows)
{
    const int warp = threadIdx.x >> 5;
    const int lane = threadIdx.x & 31;
    const int row  = blockIdx.x * WARPS_PER_BLOCK + warp;

    float loss = 0.0f;

    if (row < nrows) {
        const float4* zr = reinterpret_cast<const float4*>(z) + (size_t)row * (D / 4);
        const float4* pr = reinterpret_cast<const float4*>(p) + (size_t)row * (D / 4);

        // Each lane owns 8 z-values: float4 at [lane] and [lane+32] (coalesced).
        float4 z0 = zr[lane];
        float4 z1 = zr[lane + 32];

        // row max (softmax stability)
        float m = fmaxf(fmaxf(z0.x, z0.y), fmaxf(z0.z, z0.w));
        m = fmaxf(m, fmaxf(fmaxf(z1.x, z1.y), fmaxf(z1.z, z1.w)));
        #pragma unroll
        for (int o = 16; o > 0; o >>= 1)
            m = fmaxf(m, __shfl_xor_sync(0xffffffff, m, o));

        float e0 = __expf(z0.x - m);
        float e1 = __expf(z0.y - m);
        float e2 = __expf(z0.z - m);
        float e3 = __expf(z0.w - m);
        float e4 = __expf(z1.x - m);
        float e5 = __expf(z1.y - m);
        float e6 = __expf(z1.z - m);
        float e7 = __expf(z1.w - m);

        float4 p0v = pr[lane];
        float4 p1v = pr[lane + 32];

        float se = ((e0 + e1) + (e2 + e3)) + ((e4 + e5) + (e6 + e7));
        float sd = e0 * p0v.x + e1 * p0v.y + e2 * p0v.z + e3 * p0v.w
                 + e4 * p1v.x + e5 * p1v.y + e6 * p1v.z + e7 * p1v.w;

        #pragma unroll
        for (int o = 16; o > 0; o >>= 1) {
            se += __shfl_xor_sync(0xffffffff, se, o);
            sd += __shfl_xor_sync(0xffffffff, sd, o);
        }

        // (1 - res^0.5)/0.5 == 2*(1 - sqrt(res))
        loss = 2.0f * (1.0f - sqrtf(sd / se));
    }

    __shared__ float s[WARPS_PER_BLOCK];
    if (lane == 0) s[warp] = loss;
    __syncthreads();

    if (threadIdx.x == 0) {
        float t = 0.0f;
        #pragma unroll
        for (int i = 0; i < WARPS_PER_BLOCK; i++) t += s[i];
        g_partials[blockIdx.x] = t;
    }
}

__global__ void finalize_kernel(float* __restrict__ out, int nblocks, float inv_n)
{
    __shared__ float s[256];
    float t = 0.0f;
    for (int i = threadIdx.x; i < nblocks; i += 256) t += g_partials[i];
    s[threadIdx.x] = t;
    __syncthreads();
    #pragma unroll
    for (int o = 128; o > 0; o >>= 1) {
        if (threadIdx.x < o) s[threadIdx.x] += s[threadIdx.x + o];
        __syncthreads();
    }
    if (threadIdx.x == 0) out[0] = s[0] * inv_n;
}

extern "C" void kernel_launch(void* const* d_in, const int* in_sizes, int n_in,
                              void* d_out, int out_size)
{
    const float* z = (const float*)d_in[0];
    const float* p = (const float*)d_in[1];
    float* out = (float*)d_out;

    const int nrows = in_sizes[0] / D;
    const int nblocks = (nrows + WARPS_PER_BLOCK - 1) / WARPS_PER_BLOCK;

    row_loss_kernel<<<nblocks, THREADS>>>(z, p, nrows);
    finalize_kernel<<<1, 256>>>(out, nblocks, 1.0f / (float)nrows);
}

// round 2
// speedup vs baseline: 1.0259x; 1.0259x over previous
#include <cuda_runtime.h>

// z [N,256] fp32, p [N,256] fp32.
// res_i = sum_j softmax(z_i)_j * p_ij ; out = mean_i 2*(1 - sqrt(res_i))
// Single fused kernel: persistent grid, per-warp rows, last-block final reduce.

#define D 256
#define WARPS_PER_BLOCK 8
#define THREADS (WARPS_PER_BLOCK * 32)
#define GRID_BLOCKS 1184          // 148 SMs * 8 blocks

__device__ float g_partials[GRID_BLOCKS];
__device__ unsigned int g_count;   // zero-initialized; atomicInc wraps back to 0

__global__ __launch_bounds__(THREADS)
void fused_loss_kernel(const float* __restrict__ z,
                       const float* __restrict__ p,
                       float* __restrict__ out,
                       int nrows, float inv_n)
{
    const int warp = threadIdx.x >> 5;
    const int lane = threadIdx.x & 31;
    const int gwarp = blockIdx.x * WARPS_PER_BLOCK + warp;
    const int total_warps = gridDim.x * WARPS_PER_BLOCK;

    float wloss = 0.0f;

    for (int row = gwarp; row < nrows; row += total_warps) {
        const float4* zr = reinterpret_cast<const float4*>(z) + (size_t)row * (D / 4);
        const float4* pr = reinterpret_cast<const float4*>(p) + (size_t)row * (D / 4);

        float4 z0 = zr[lane];
        float4 z1 = zr[lane + 32];
        float4 p0v = pr[lane];
        float4 p1v = pr[lane + 32];

        float m = fmaxf(fmaxf(z0.x, z0.y), fmaxf(z0.z, z0.w));
        m = fmaxf(m, fmaxf(fmaxf(z1.x, z1.y), fmaxf(z1.z, z1.w)));
        #pragma unroll
        for (int o = 16; o > 0; o >>= 1)
            m = fmaxf(m, __shfl_xor_sync(0xffffffff, m, o));

        float e0 = __expf(z0.x - m);
        float e1 = __expf(z0.y - m);
        float e2 = __expf(z0.z - m);
        float e3 = __expf(z0.w - m);
        float e4 = __expf(z1.x - m);
        float e5 = __expf(z1.y - m);
        float e6 = __expf(z1.z - m);
        float e7 = __expf(z1.w - m);

        float se = ((e0 + e1) + (e2 + e3)) + ((e4 + e5) + (e6 + e7));
        float sd = e0 * p0v.x + e1 * p0v.y + e2 * p0v.z + e3 * p0v.w
                 + e4 * p1v.x + e5 * p1v.y + e6 * p1v.z + e7 * p1v.w;

        #pragma unroll
        for (int o = 16; o > 0; o >>= 1) {
            se += __shfl_xor_sync(0xffffffff, se, o);
            sd += __shfl_xor_sync(0xffffffff, sd, o);
        }

        wloss += 2.0f * (1.0f - sqrtf(sd / se));
    }

    // block partial (deterministic fixed-order sum over 8 warps)
    __shared__ float s[WARPS_PER_BLOCK];
    if (lane == 0) s[warp] = wloss;
    __syncthreads();

    __shared__ bool is_last;
    if (threadIdx.x == 0) {
        float t = 0.0f;
        #pragma unroll
        for (int i = 0; i < WARPS_PER_BLOCK; i++) t += s[i];
        g_partials[blockIdx.x] = t;
        __threadfence();
        // wraps to 0 after the final block -> re-armed for next graph replay
        unsigned int prev = atomicInc(&g_count, gridDim.x - 1);
        is_last = (prev == gridDim.x - 1);
    }
    __syncthreads();

    if (is_last) {
        // final reduce of gridDim.x partials, deterministic order
        __shared__ float r[THREADS];
        float t = 0.0f;
        for (int i = threadIdx.x; i < (int)gridDim.x; i += THREADS)
            t += g_partials[i];
        r[threadIdx.x] = t;
        __syncthreads();
        #pragma unroll
        for (int o = THREADS / 2; o > 0; o >>= 1) {
            if (threadIdx.x < o) r[threadIdx.x] += r[threadIdx.x + o];
            __syncthreads();
        }
        if (threadIdx.x == 0) out[0] = r[0] * inv_n;
    }
}

extern "C" void kernel_launch(void* const* d_in, const int* in_sizes, int n_in,
                              void* d_out, int out_size)
{
    const float* z = (const float*)d_in[0];
    const float* p = (const float*)d_in[1];
    float* out = (float*)d_out;

    const int nrows = in_sizes[0] / D;

    fused_loss_kernel<<<GRID_BLOCKS, THREADS>>>(z, p, out, nrows, 1.0f / (float)nrows);
}